// round 2
// baseline (speedup 1.0000x reference)
#include <cuda_runtime.h>
#include <math.h>

// Persistent device scratch (no allocation allowed in kernel_launch).
__device__ float g_master_pos[3];
__device__ float g_score[100000];

// Kernel 1: locate the master node (x_t[i,0] == 1.0) and stash its position.
// Exactly one node matches per setup, so a plain (single-writer) store is fine.
__global__ void find_master_kernel(const float* __restrict__ x_t, int n_nodes) {
    int i = blockIdx.x * blockDim.x + threadIdx.x;
    if (i < n_nodes) {
        if (__ldg(&x_t[i * 7]) == 1.0f) {
            g_master_pos[0] = x_t[i * 7 + 1];
            g_master_pos[1] = x_t[i * 7 + 2];
            g_master_pos[2] = x_t[i * 7 + 3];
        }
    }
}

// Kernel 2: per-node feature computation + MLP (3 -> 32 -> 32 -> 1) + sigmoid.
// One thread per node; weights cached in shared memory (broadcast reads).
__global__ void node_score_kernel(const float* __restrict__ x_t,
                                  const float* __restrict__ x_t_dt,
                                  const float* __restrict__ W1,
                                  const float* __restrict__ b1,
                                  const float* __restrict__ W2,
                                  const float* __restrict__ b2,
                                  const float* __restrict__ W3,
                                  const float* __restrict__ b3,
                                  int n_nodes) {
    __shared__ float sW1[96];
    __shared__ float sb1[32];
    __shared__ float sW2[1024];
    __shared__ float sb2[32];
    __shared__ float sW3[32];
    __shared__ float sb3;
    __shared__ float smx, smy, smz;

    int t = threadIdx.x;
    for (int k = t; k < 96; k += blockDim.x) sW1[k] = W1[k];
    for (int k = t; k < 1024; k += blockDim.x) sW2[k] = W2[k];
    if (t < 32) {
        sb1[t] = b1[t];
        sb2[t] = b2[t];
        sW3[t] = W3[t];
    }
    if (t == 0) {
        sb3 = b3[0];
        smx = g_master_pos[0];
        smy = g_master_pos[1];
        smz = g_master_pos[2];
    }
    __syncthreads();

    int i = blockIdx.x * blockDim.x + t;
    if (i >= n_nodes) return;

    // Positions / displacement
    float px = x_t[i * 7 + 1];
    float py = x_t[i * 7 + 2];
    float pz = x_t[i * 7 + 3];
    float dx = x_t_dt[i * 7 + 1] - px;
    float dy = x_t_dt[i * 7 + 2] - py;
    float dz = x_t_dt[i * 7 + 3] - pz;

    float dn = sqrtf(dx * dx + dy * dy + dz * dz);   // velocity_score = ||disp||
    float inv_dn = 1.0f / fmaxf(dn, 1e-12f);         // dt = 1
    float vx = dx * inv_dn, vy = dy * inv_dn, vz = dz * inv_dn;

    float rx = px - smx, ry = py - smy, rz = pz - smz;
    float rn = sqrtf(rx * rx + ry * ry + rz * rz);
    float dist = rn + 1e-6f;
    float na = fmaxf(rn, 1e-6f);
    float nb = fmaxf(sqrtf(vx * vx + vy * vy + vz * vz), 1e-6f);
    float dir_score = (rx * vx + ry * vy + rz * vz) / (na * nb);

    float a0 = 1.0f / dist;   // distance_score
    float a1 = dir_score;     // direction_score
    float a2 = dn;            // velocity_score

    // Layer 1: 3 -> 32
    float h[32];
#pragma unroll
    for (int j = 0; j < 32; j++) {
        float s = fmaf(a2, sW1[j * 3 + 2],
                 fmaf(a1, sW1[j * 3 + 1],
                 fmaf(a0, sW1[j * 3 + 0], sb1[j])));
        h[j] = fmaxf(s, 0.0f);
    }

    // Layer 2: 32 -> 32
    float h2[32];
#pragma unroll
    for (int j = 0; j < 32; j++) {
        float s = sb2[j];
#pragma unroll
        for (int k = 0; k < 32; k++) s = fmaf(h[k], sW2[j * 32 + k], s);
        h2[j] = fmaxf(s, 0.0f);
    }

    // Layer 3: 32 -> 1, sigmoid
    float s = sb3;
#pragma unroll
    for (int k = 0; k < 32; k++) s = fmaf(h2[k], sW3[k], s);
    g_score[i] = 1.0f / (1.0f + expf(-s));
}

// Kernel 3: gather node scores per edge (uses only edge_index row 1 = targets).
// Indices are int32 (JAX x64 disabled downcasts int64 -> int32).
// 4 edges per thread: one 16B index load + one 16B store; the 400KB score
// table stays L2-resident so random gathers are L2-served.
__global__ void gather_kernel(const int* __restrict__ tgt,
                              float* __restrict__ out,
                              int n_edges) {
    int j = blockIdx.x * blockDim.x + threadIdx.x;
    int n4 = n_edges >> 2;
    if (j < n4) {
        int4 a = reinterpret_cast<const int4*>(tgt)[j];
        float4 o;
        o.x = g_score[a.x];
        o.y = g_score[a.y];
        o.z = g_score[a.z];
        o.w = g_score[a.w];
        reinterpret_cast<float4*>(out)[j] = o;
    }
    // Tail (n_edges % 4): handled by thread 0 (empty for 6.4M edges).
    if (j == 0) {
        for (int e = n4 << 2; e < n_edges; e++) {
            out[e] = g_score[tgt[e]];
        }
    }
}

extern "C" void kernel_launch(void* const* d_in, const int* in_sizes, int n_in,
                              void* d_out, int out_size) {
    const float* x_t    = (const float*)d_in[0];
    const float* x_t_dt = (const float*)d_in[1];
    const int*   edge_index = (const int*)d_in[2];   // int32! (JAX x64 off)
    const float* W1 = (const float*)d_in[3];
    const float* b1 = (const float*)d_in[4];
    const float* W2 = (const float*)d_in[5];
    const float* b2 = (const float*)d_in[6];
    const float* W3 = (const float*)d_in[7];
    const float* b3 = (const float*)d_in[8];
    float* out = (float*)d_out;

    int n_nodes = in_sizes[0] / 7;
    int n_edges = in_sizes[2] / 2;
    const int* tgt = edge_index + n_edges;  // row 1 of (2, E)

    int threads = 256;
    int nb_nodes = (n_nodes + threads - 1) / threads;
    find_master_kernel<<<nb_nodes, threads>>>(x_t, n_nodes);
    node_score_kernel<<<nb_nodes, threads>>>(x_t, x_t_dt, W1, b1, W2, b2, W3, b3, n_nodes);

    int n4 = n_edges >> 2;
    int nb_gather = (n4 + threads - 1) / threads;
    gather_kernel<<<nb_gather, threads>>>(tgt, out, n_edges);
}

// round 3
// speedup vs baseline: 2.2208x; 2.2208x over previous
#include <cuda_runtime.h>
#include <cuda_fp16.h>
#include <math.h>

// Persistent device scratch (no allocation allowed in kernel_launch).
__device__ float  g_master_pos[3];
__device__ __half g_score_h[100032];   // fp16 score table (padded)

// ---------------------------------------------------------------------------
// Kernel 1: locate master node. Coalesced linear scan of all 7*N floats;
// a hit only counts if it sits in column 0 (j % 7 == 0).
// ---------------------------------------------------------------------------
__global__ void find_master_kernel(const float* __restrict__ x_t, int total) {
    int j = blockIdx.x * blockDim.x + threadIdx.x;
    if (j < total) {
        float v = __ldg(&x_t[j]);
        if (v == 1.0f && (j % 7) == 0) {
            g_master_pos[0] = x_t[j + 1];
            g_master_pos[1] = x_t[j + 2];
            g_master_pos[2] = x_t[j + 3];
        }
    }
}

// ---------------------------------------------------------------------------
// Kernel 2: per-node features + MLP (3->32->32->1) + sigmoid -> fp16 table.
// Inputs staged coalesced into SMEM; W2 read as float4 (LDS.128).
// ---------------------------------------------------------------------------
#define NS_THREADS 256
__global__ void node_score_kernel(const float* __restrict__ x_t,
                                  const float* __restrict__ x_t_dt,
                                  const float* __restrict__ W1,
                                  const float* __restrict__ b1,
                                  const float* __restrict__ W2,
                                  const float* __restrict__ b2,
                                  const float* __restrict__ W3,
                                  const float* __restrict__ b3,
                                  int n_nodes) {
    __shared__ float sW1[96];
    __shared__ float sb1[32];
    __shared__ __align__(16) float sW2[1024];
    __shared__ float sb2[32];
    __shared__ float sW3[32];
    __shared__ float sb3;
    __shared__ float smx, smy, smz;
    __shared__ __align__(16) float sx[NS_THREADS * 7];
    __shared__ __align__(16) float sxd[NS_THREADS * 7];

    int t = threadIdx.x;
    for (int k = t; k < 96; k += NS_THREADS) sW1[k] = W1[k];
    for (int k = t; k < 1024; k += NS_THREADS) sW2[k] = W2[k];
    if (t < 32) {
        sb1[t] = b1[t];
        sb2[t] = b2[t];
        sW3[t] = W3[t];
    }
    if (t == 0) {
        sb3 = b3[0];
        smx = g_master_pos[0];
        smy = g_master_pos[1];
        smz = g_master_pos[2];
    }

    // Coalesced staging of this block's node rows.
    int base_node = blockIdx.x * NS_THREADS;
    int nrows = min(NS_THREADS, n_nodes - base_node);
    int nflt = nrows * 7;
    const float* xr  = x_t    + (size_t)base_node * 7;
    const float* xdr = x_t_dt + (size_t)base_node * 7;
    for (int k = t; k < nflt; k += NS_THREADS) {
        sx[k]  = xr[k];
        sxd[k] = xdr[k];
    }
    __syncthreads();

    if (t >= nrows) return;
    int i = base_node + t;

    float px = sx[t * 7 + 1];
    float py = sx[t * 7 + 2];
    float pz = sx[t * 7 + 3];
    float dx = sxd[t * 7 + 1] - px;
    float dy = sxd[t * 7 + 2] - py;
    float dz = sxd[t * 7 + 3] - pz;

    float dn = sqrtf(dx * dx + dy * dy + dz * dz);   // velocity_score
    float inv_dn = 1.0f / fmaxf(dn, 1e-12f);         // dt = 1
    float vx = dx * inv_dn, vy = dy * inv_dn, vz = dz * inv_dn;

    float rx = px - smx, ry = py - smy, rz = pz - smz;
    float rn = sqrtf(rx * rx + ry * ry + rz * rz);
    float dist = rn + 1e-6f;
    float na = fmaxf(rn, 1e-6f);
    float nb = fmaxf(sqrtf(vx * vx + vy * vy + vz * vz), 1e-6f);
    float dir_score = (rx * vx + ry * vy + rz * vz) / (na * nb);

    float a0 = 1.0f / dist;
    float a1 = dir_score;
    float a2 = dn;

    // Layer 1: 3 -> 32
    float h[32];
#pragma unroll
    for (int j = 0; j < 32; j++) {
        float s = fmaf(a2, sW1[j * 3 + 2],
                 fmaf(a1, sW1[j * 3 + 1],
                 fmaf(a0, sW1[j * 3 + 0], sb1[j])));
        h[j] = fmaxf(s, 0.0f);
    }

    // Layer 2: 32 -> 32 with vectorized weight reads (LDS.128)
    const float4* w2v = reinterpret_cast<const float4*>(sW2);
    float h2[32];
#pragma unroll
    for (int j = 0; j < 32; j++) {
        float s = sb2[j];
#pragma unroll
        for (int k4 = 0; k4 < 8; k4++) {
            float4 w = w2v[j * 8 + k4];
            s = fmaf(h[k4 * 4 + 0], w.x, s);
            s = fmaf(h[k4 * 4 + 1], w.y, s);
            s = fmaf(h[k4 * 4 + 2], w.z, s);
            s = fmaf(h[k4 * 4 + 3], w.w, s);
        }
        h2[j] = fmaxf(s, 0.0f);
    }

    // Layer 3: 32 -> 1, sigmoid
    float s = sb3;
#pragma unroll
    for (int k = 0; k < 32; k++) s = fmaf(h2[k], sW3[k], s);
    float sig = 1.0f / (1.0f + __expf(-s));
    g_score_h[i] = __float2half(sig);
}

// ---------------------------------------------------------------------------
// Kernel 3: persistent gather. Each block copies the full fp16 score table
// into SMEM (200KB), then streams edges: int4 index load -> 4x LDS.U16 ->
// float4 store. Random gathers never touch L2; kernel runs at the DRAM
// roofline of the 51.2MB index+output stream.
// ---------------------------------------------------------------------------
#define G_THREADS 1024
__global__ void gather_kernel(const int* __restrict__ tgt,
                              float* __restrict__ out,
                              int n_edges, int n_nodes) {
    extern __shared__ __align__(16) __half stab[];

    // Cooperative table load (uint4 = 8 halves, coalesced).
    int n8 = (n_nodes + 7) >> 3;
    const uint4* src = reinterpret_cast<const uint4*>(g_score_h);
    uint4* dst = reinterpret_cast<uint4*>(stab);
    for (int k = threadIdx.x; k < n8; k += G_THREADS) dst[k] = src[k];
    __syncthreads();

    int n4 = n_edges >> 2;
    int stride = gridDim.x * G_THREADS;
    const int4* tv = reinterpret_cast<const int4*>(tgt);
    float4* ov = reinterpret_cast<float4*>(out);

    for (int j = blockIdx.x * G_THREADS + threadIdx.x; j < n4; j += stride) {
        int4 a = tv[j];
        float4 o;
        o.x = __half2float(stab[a.x]);
        o.y = __half2float(stab[a.y]);
        o.z = __half2float(stab[a.z]);
        o.w = __half2float(stab[a.w]);
        ov[j] = o;
    }

    // Tail (n_edges % 4)
    if (blockIdx.x == 0 && threadIdx.x == 0) {
        for (int e = n4 << 2; e < n_edges; e++)
            out[e] = __half2float(stab[tgt[e]]);
    }
}

extern "C" void kernel_launch(void* const* d_in, const int* in_sizes, int n_in,
                              void* d_out, int out_size) {
    const float* x_t    = (const float*)d_in[0];
    const float* x_t_dt = (const float*)d_in[1];
    const int*   edge_index = (const int*)d_in[2];   // int32 (JAX x64 off)
    const float* W1 = (const float*)d_in[3];
    const float* b1 = (const float*)d_in[4];
    const float* W2 = (const float*)d_in[5];
    const float* b2 = (const float*)d_in[6];
    const float* W3 = (const float*)d_in[7];
    const float* b3 = (const float*)d_in[8];
    float* out = (float*)d_out;

    int n_nodes = in_sizes[0] / 7;
    int n_edges = in_sizes[2] / 2;
    const int* tgt = edge_index + n_edges;  // row 1 of (2, E)

    // Kernel 1: coalesced master scan over all 7*N floats.
    int total = n_nodes * 7;
    find_master_kernel<<<(total + 255) / 256, 256>>>(x_t, total);

    // Kernel 2: node scores.
    int nb_nodes = (n_nodes + NS_THREADS - 1) / NS_THREADS;
    node_score_kernel<<<nb_nodes, NS_THREADS>>>(x_t, x_t_dt, W1, b1, W2, b2, W3, b3, n_nodes);

    // Kernel 3: persistent gather with SMEM-resident fp16 table.
    size_t smem = ((size_t)(n_nodes + 7) & ~7ull) * sizeof(__half);
    static bool attr_set = false;
    if (!attr_set) {
        cudaFuncSetAttribute(gather_kernel,
                             cudaFuncAttributeMaxDynamicSharedMemorySize,
                             (int)smem + 16);
        attr_set = true;
    }
    gather_kernel<<<148, G_THREADS, smem>>>(tgt, out, n_edges, n_nodes);
}